// round 5
// baseline (speedup 1.0000x reference)
#include <cuda_runtime.h>

#define P_CONST 5.0f
#define A_CONST 10.0f
#define MAX_CLAUSES 1000000
#define LOSS_BLOCKS 592   // one full wave at 4 blocks/SM on 148 SMs

// Scratch (zero-initialized at load; kernels restore zero/overwritten state
// each replay so the graph is deterministic).
__device__ float2 g_acc[MAX_CLAUSES];
__device__ float g_partial[LOSS_BLOCKS];   // per-block partials, plain stores
__device__ unsigned int g_done;

// ---------------------------------------------------------------------------
// Kernel 1: edge scatter, 4 pos + 4 neg edges per thread.
// Index rows loaded as int4 with streaming hint; (lit*w, w) accumulated with
// ONE float2 atomic (RED.64) per edge. At the LTS-sector roofline.
// ---------------------------------------------------------------------------
__device__ __forceinline__ void scatter_edge(const float* __restrict__ x,
                                             int c, int v, bool neg)
{
    float lit = __ldg(x + v);
    if (neg) lit = 1.0f - lit;
    float w = __expf(P_CONST * lit);
    atomicAdd(reinterpret_cast<float2*>(&g_acc[c]), make_float2(lit * w, w));
}

__global__ void __launch_bounds__(256) edge_kernel(
    const float* __restrict__ x,
    const int* __restrict__ adj_pos,   // [2, E]: row 0 = clause, row 1 = var
    const int* __restrict__ adj_neg,   // [2, E]
    int E4)                            // E/4
{
    int i = blockIdx.x * blockDim.x + threadIdx.x;
    if (i >= E4) return;

    const int E = E4 * 4;
    const int4* cp4 = reinterpret_cast<const int4*>(adj_pos);
    const int4* vp4 = reinterpret_cast<const int4*>(adj_pos + E);
    const int4* cn4 = reinterpret_cast<const int4*>(adj_neg);
    const int4* vn4 = reinterpret_cast<const int4*>(adj_neg + E);

    int4 cp = __ldcs(cp4 + i);
    int4 vp = __ldcs(vp4 + i);
    int4 cn = __ldcs(cn4 + i);
    int4 vn = __ldcs(vn4 + i);

    scatter_edge(x, cp.x, vp.x, false);
    scatter_edge(x, cp.y, vp.y, false);
    scatter_edge(x, cp.z, vp.z, false);
    scatter_edge(x, cp.w, vp.w, false);

    scatter_edge(x, cn.x, vn.x, true);
    scatter_edge(x, cn.y, vn.y, true);
    scatter_edge(x, cn.z, vn.z, true);
    scatter_edge(x, cn.w, vn.w, true);
}

// ---------------------------------------------------------------------------
// Kernel 2: per-clause sigmoid + squared error (2 clauses/thread/iter, float4),
// re-zeroing g_acc as it goes. Block partials go to g_partial via plain
// stores; the last-done block sums them and writes the mean to out.
// ---------------------------------------------------------------------------
__global__ void __launch_bounds__(256) loss_kernel(
    const float* __restrict__ clause_count, int C2, float* out, float invC)
{
    float4* acc4 = reinterpret_cast<float4*>(g_acc);
    const float2* cc2 = reinterpret_cast<const float2*>(clause_count);
    const float4 z4 = make_float4(0.f, 0.f, 0.f, 0.f);

    float local = 0.0f;
    int stride = gridDim.x * blockDim.x;
    for (int i = blockIdx.x * blockDim.x + threadIdx.x; i < C2; i += stride) {
        float4 a = acc4[i];          // clauses 2i (x,y) and 2i+1 (z,w)
        float2 c = cc2[i];
        acc4[i] = z4;                // re-zero for next replay

        float m0 = a.x / a.y;
        float m1 = a.z / a.w;
        float s0 = 1.0f / (1.0f + __expf(-A_CONST * (m0 - 0.5f)));
        float s1 = 1.0f / (1.0f + __expf(-A_CONST * (m1 - 0.5f)));
        float d0 = s0 - c.x;
        float d1 = s1 - c.y;
        local += d0 * d0 + d1 * d1;
    }

    // intra-block reduce
    #pragma unroll
    for (int off = 16; off > 0; off >>= 1)
        local += __shfl_down_sync(0xffffffffu, local, off);

    __shared__ float warp_sums[8];
    __shared__ bool is_last;
    int lane = threadIdx.x & 31;
    int wid = threadIdx.x >> 5;
    if (lane == 0) warp_sums[wid] = local;
    __syncthreads();

    if (wid == 0) {
        float s = (lane < (blockDim.x >> 5)) ? warp_sums[lane] : 0.0f;
        #pragma unroll
        for (int off = 4; off > 0; off >>= 1)
            s += __shfl_down_sync(0xffffffffu, s, off);
        if (lane == 0) {
            g_partial[blockIdx.x] = s;       // plain store, distinct address
            __threadfence();
            unsigned int ticket = atomicAdd(&g_done, 1u);
            is_last = (ticket == gridDim.x - 1);
        }
    }
    __syncthreads();

    // last block: sum all partials in double, finalize
    if (is_last) {
        __threadfence();  // acquire: make other blocks' partials visible
        double acc = 0.0;
        for (int i = threadIdx.x; i < (int)gridDim.x; i += blockDim.x)
            acc += (double)g_partial[i];

        #pragma unroll
        for (int off = 16; off > 0; off >>= 1)
            acc += __shfl_down_sync(0xffffffffu, acc, off);

        __shared__ double dsums[8];
        if (lane == 0) dsums[wid] = acc;
        __syncthreads();
        if (wid == 0) {
            double t = (lane < (blockDim.x >> 5)) ? dsums[lane] : 0.0;
            #pragma unroll
            for (int off = 4; off > 0; off >>= 1)
                t += __shfl_down_sync(0xffffffffu, t, off);
            if (lane == 0) {
                *out = (float)(t * (double)invC);
                g_done = 0u;   // reset for next replay
            }
        }
    }
}

// ---------------------------------------------------------------------------
// Launch
// Inputs (metadata order): xv f32 [V], adj_pos i32 [2*E], adj_neg i32 [2*E],
//                          clause_count f32 [C]. Output: f32 scalar loss.
// ---------------------------------------------------------------------------
extern "C" void kernel_launch(void* const* d_in, const int* in_sizes, int n_in,
                              void* d_out, int out_size)
{
    const float* xv = (const float*)d_in[0];
    const int*   ap = (const int*)d_in[1];
    const int*   an = (const int*)d_in[2];
    const float* cc = (const float*)d_in[3];
    float* out = (float*)d_out;

    int E = in_sizes[1] / 2;   // 3,000,000
    int C = in_sizes[3];       // 1,000,000
    int E4 = E / 4;

    const int T = 256;
    int edge_blocks = (E4 + T - 1) / T;
    edge_kernel<<<edge_blocks, T>>>(xv, ap, an, E4);

    loss_kernel<<<LOSS_BLOCKS, T>>>(cc, C / 2, out, 1.0f / (float)C);
}

// round 6
// speedup vs baseline: 1.1293x; 1.1293x over previous
#include <cuda_runtime.h>

#define P_CONST 5.0f
#define A_CONST 10.0f
#define MAX_CLAUSES 1000000
#define MAX_LOSS_BLOCKS 4096

// Scratch (zero-initialized at load; loss_kernel's atomicExch restores the
// all-zero state each replay, so graph replays are deterministic).
__device__ float2 g_acc[MAX_CLAUSES];
__device__ float g_partial[MAX_LOSS_BLOCKS];
__device__ unsigned int g_done;

// ---------------------------------------------------------------------------
// Kernel 1: edge scatter, 4 pos + 4 neg edges per thread.
// Index rows loaded as int4 with streaming hint; (lit*w, w) accumulated with
// ONE float2 atomic (RED.64) per edge. At the LTS-sector roofline.
// ---------------------------------------------------------------------------
__device__ __forceinline__ void scatter_edge(const float* __restrict__ x,
                                             int c, int v, bool neg)
{
    float lit = __ldg(x + v);
    if (neg) lit = 1.0f - lit;
    float w = __expf(P_CONST * lit);
    atomicAdd(reinterpret_cast<float2*>(&g_acc[c]), make_float2(lit * w, w));
}

__global__ void __launch_bounds__(256) edge_kernel(
    const float* __restrict__ x,
    const int* __restrict__ adj_pos,   // [2, E]: row 0 = clause, row 1 = var
    const int* __restrict__ adj_neg,   // [2, E]
    int E4)                            // E/4
{
    int i = blockIdx.x * blockDim.x + threadIdx.x;
    if (i >= E4) return;

    const int E = E4 * 4;
    const int4* cp4 = reinterpret_cast<const int4*>(adj_pos);
    const int4* vp4 = reinterpret_cast<const int4*>(adj_pos + E);
    const int4* cn4 = reinterpret_cast<const int4*>(adj_neg);
    const int4* vn4 = reinterpret_cast<const int4*>(adj_neg + E);

    int4 cp = __ldcs(cp4 + i);
    int4 vp = __ldcs(vp4 + i);
    int4 cn = __ldcs(cn4 + i);
    int4 vn = __ldcs(vn4 + i);

    scatter_edge(x, cp.x, vp.x, false);
    scatter_edge(x, cp.y, vp.y, false);
    scatter_edge(x, cp.z, vp.z, false);
    scatter_edge(x, cp.w, vp.w, false);

    scatter_edge(x, cn.x, vn.x, true);
    scatter_edge(x, cn.y, vn.y, true);
    scatter_edge(x, cn.z, vn.z, true);
    scatter_edge(x, cn.w, vn.w, true);
}

// ---------------------------------------------------------------------------
// Kernel 2: per-clause sigmoid + squared error. One clause-pair per thread.
// atomicExch.64 reads each (num,den) pair AND zeroes it in a single L2 RMW —
// no separate re-zero store. Block partials via plain stores; last-done
// block sums them in double and writes the mean.
// ---------------------------------------------------------------------------
__global__ void __launch_bounds__(256) loss_kernel(
    const float* __restrict__ clause_count, int C2, float* out, float invC)
{
    unsigned long long* acc = reinterpret_cast<unsigned long long*>(g_acc);
    const float2* cc2 = reinterpret_cast<const float2*>(clause_count);

    int i = blockIdx.x * blockDim.x + threadIdx.x;
    float local = 0.0f;
    if (i < C2) {
        // clauses 2i and 2i+1: exchange-with-zero returns (num,den) packed
        unsigned long long a0 = atomicExch(&acc[2 * i], 0ull);
        unsigned long long a1 = atomicExch(&acc[2 * i + 1], 0ull);
        float2 c = __ldcs(cc2 + i);

        float2 v0 = *reinterpret_cast<float2*>(&a0);
        float2 v1 = *reinterpret_cast<float2*>(&a1);

        float m0 = v0.x / v0.y;
        float m1 = v1.x / v1.y;
        float s0 = 1.0f / (1.0f + __expf(-A_CONST * (m0 - 0.5f)));
        float s1 = 1.0f / (1.0f + __expf(-A_CONST * (m1 - 0.5f)));
        float d0 = s0 - c.x;
        float d1 = s1 - c.y;
        local = d0 * d0 + d1 * d1;
    }

    // intra-block reduce
    #pragma unroll
    for (int off = 16; off > 0; off >>= 1)
        local += __shfl_down_sync(0xffffffffu, local, off);

    __shared__ float warp_sums[8];
    __shared__ bool is_last;
    int lane = threadIdx.x & 31;
    int wid = threadIdx.x >> 5;
    if (lane == 0) warp_sums[wid] = local;
    __syncthreads();

    if (wid == 0) {
        float s = (lane < (blockDim.x >> 5)) ? warp_sums[lane] : 0.0f;
        #pragma unroll
        for (int off = 4; off > 0; off >>= 1)
            s += __shfl_down_sync(0xffffffffu, s, off);
        if (lane == 0) {
            g_partial[blockIdx.x] = s;       // plain store, distinct address
            __threadfence();
            unsigned int ticket = atomicAdd(&g_done, 1u);
            is_last = (ticket == gridDim.x - 1);
        }
    }
    __syncthreads();

    // last block: sum all partials in double, finalize
    if (is_last) {
        __threadfence();  // make other blocks' partials visible
        double acc_d = 0.0;
        for (int k = threadIdx.x; k < (int)gridDim.x; k += blockDim.x)
            acc_d += (double)g_partial[k];

        #pragma unroll
        for (int off = 16; off > 0; off >>= 1)
            acc_d += __shfl_down_sync(0xffffffffu, acc_d, off);

        __shared__ double dsums[8];
        if (lane == 0) dsums[wid] = acc_d;
        __syncthreads();
        if (wid == 0) {
            double t = (lane < (blockDim.x >> 5)) ? dsums[lane] : 0.0;
            #pragma unroll
            for (int off = 4; off > 0; off >>= 1)
                t += __shfl_down_sync(0xffffffffu, t, off);
            if (lane == 0) {
                *out = (float)(t * (double)invC);
                g_done = 0u;   // reset for next replay
            }
        }
    }
}

// ---------------------------------------------------------------------------
// Launch
// Inputs (metadata order): xv f32 [V], adj_pos i32 [2*E], adj_neg i32 [2*E],
//                          clause_count f32 [C]. Output: f32 scalar loss.
// ---------------------------------------------------------------------------
extern "C" void kernel_launch(void* const* d_in, const int* in_sizes, int n_in,
                              void* d_out, int out_size)
{
    const float* xv = (const float*)d_in[0];
    const int*   ap = (const int*)d_in[1];
    const int*   an = (const int*)d_in[2];
    const float* cc = (const float*)d_in[3];
    float* out = (float*)d_out;

    int E = in_sizes[1] / 2;   // 3,000,000
    int C = in_sizes[3];       // 1,000,000
    int E4 = E / 4;
    int C2 = C / 2;

    const int T = 256;
    int edge_blocks = (E4 + T - 1) / T;
    edge_kernel<<<edge_blocks, T>>>(xv, ap, an, E4);

    int loss_blocks = (C2 + T - 1) / T;   // 1954 for C=1M (< MAX_LOSS_BLOCKS)
    loss_kernel<<<loss_blocks, T>>>(cc, C2, out, 1.0f / (float)C);
}